// round 2
// baseline (speedup 1.0000x reference)
#include <cuda_runtime.h>
#include <math.h>

#define BB 2
#define SS 2048
#define EE 1024
#define HH 16
#define DD 64
#define MAXREL 512

// ---------------- device scratch (allocation-free: device globals, 64MB) ----
__device__ float g_Qh[BB * HH * SS * DD];   // [B,H,S,D]
__device__ float g_Kh[BB * HH * SS * DD];
__device__ float g_Vh[BB * HH * SS * DD];
__device__ float g_Oh[BB * HH * SS * DD];

// ---------------- fused QKV projection: X @ W^T + b -> [B,H,S,D] ------------
// grid: (EE/64, (BB*SS)/64, 3), block: 256
__global__ __launch_bounds__(256) void proj_qkv_kernel(
    const float* __restrict__ Xq, const float* __restrict__ Xk, const float* __restrict__ Xv,
    const float* __restrict__ Wq, const float* __restrict__ bq,
    const float* __restrict__ Wk, const float* __restrict__ bk,
    const float* __restrict__ Wv, const float* __restrict__ bv)
{
    const int z = blockIdx.z;
    const float* X    = (z == 0) ? Xq : (z == 1) ? Xk : Xv;
    const float* W    = (z == 0) ? Wq : (z == 1) ? Wk : Wv;
    const float* bias = (z == 0) ? bq : (z == 1) ? bk : bv;
    float* dst        = (z == 0) ? g_Qh : (z == 1) ? g_Kh : g_Vh;

    __shared__ float As[16][68];
    __shared__ float Bs[16][68];

    const int m0 = blockIdx.y * 64;
    const int n0 = blockIdx.x * 64;
    const int t  = threadIdx.x;
    const int ty = t >> 4, tx = t & 15;
    const int lrow = t >> 2, lc4 = t & 3;

    float acc[4][4];
#pragma unroll
    for (int i = 0; i < 4; i++)
#pragma unroll
        for (int j = 0; j < 4; j++) acc[i][j] = 0.f;

    for (int k0 = 0; k0 < EE; k0 += 16) {
        float4 av = *(const float4*)&X[(size_t)(m0 + lrow) * EE + k0 + lc4 * 4];
        float4 wv = *(const float4*)&W[(size_t)(n0 + lrow) * EE + k0 + lc4 * 4];
        __syncthreads();
        As[lc4 * 4 + 0][lrow] = av.x; As[lc4 * 4 + 1][lrow] = av.y;
        As[lc4 * 4 + 2][lrow] = av.z; As[lc4 * 4 + 3][lrow] = av.w;
        Bs[lc4 * 4 + 0][lrow] = wv.x; Bs[lc4 * 4 + 1][lrow] = wv.y;
        Bs[lc4 * 4 + 2][lrow] = wv.z; Bs[lc4 * 4 + 3][lrow] = wv.w;
        __syncthreads();
#pragma unroll
        for (int kk = 0; kk < 16; kk++) {
            float4 a = *(const float4*)&As[kk][ty * 4];
            float4 b = *(const float4*)&Bs[kk][tx * 4];
            float ar[4] = {a.x, a.y, a.z, a.w};
            float br[4] = {b.x, b.y, b.z, b.w};
#pragma unroll
            for (int i = 0; i < 4; i++)
#pragma unroll
                for (int j = 0; j < 4; j++) acc[i][j] += ar[i] * br[j];
        }
    }

#pragma unroll
    for (int i = 0; i < 4; i++) {
        int m = m0 + ty * 4 + i;
        int b_ = m >> 11, s_ = m & 2047;
#pragma unroll
        for (int j = 0; j < 4; j++) {
            int n = n0 + tx * 4 + j;
            int h = n >> 6, d = n & 63;
            dst[(((size_t)b_ * HH + h) * SS + s_) * DD + d] = acc[i][j] + bias[n];
        }
    }
}

// ---------------- attention, spill variant (attn lives in d_out) ------------
// Two passes: pass1 computes scores + (m,l), spills raw scores into the attn
// output region; pass2 re-reads them (L2-hot), writes normalized attn, does PV.
// grid: (SS/64, BB*HH), block 256
__global__ __launch_bounds__(256) void attn_spill_kernel(
    const float* __restrict__ rtab, float* __restrict__ attn)
{
    __shared__ float SA[64][68];
    __shared__ float SB[64][68];
    __shared__ float bias_s[128];

    const int q0 = blockIdx.x * 64;
    const int bh = blockIdx.y;
    const int h  = bh & (HH - 1);
    const int t  = threadIdx.x;
    const int ty = t >> 4, tx = t & 15;
    const float scale = 0.125f;  // 1/sqrt(64)

    const float* Qb = g_Qh + (size_t)bh * SS * DD;
    const float* Kb = g_Kh + (size_t)bh * SS * DD;
    const float* Vb = g_Vh + (size_t)bh * SS * DD;
    float* attn_bh  = attn + (size_t)bh * SS * SS;

    // load Q block [64,64] into SA (covered by the sync inside the first tile)
#pragma unroll
    for (int i = 0; i < 4; i++) {
        int e = t + i * 256;
        int row = e >> 4, c4 = e & 15;
        *(float4*)&SA[row][c4 * 4] = *(const float4*)&Qb[(size_t)(q0 + row) * DD + c4 * 4];
    }

    const int ntiles = (q0 >> 6) + 1;
    float m[4], l[4];
#pragma unroll
    for (int i = 0; i < 4; i++) { m[i] = -INFINITY; l[i] = 0.f; }

    // ---------------- PASS 1: scores -> gmem (raw) + online (m, l) ----------
    for (int kt = 0; kt < ntiles; kt++) {
        const int k0 = kt * 64;
        float4 kv[4]; int krow[4], kc4[4];
#pragma unroll
        for (int i = 0; i < 4; i++) {
            int e = t + i * 256;
            krow[i] = e >> 4; kc4[i] = e & 15;
            kv[i] = *(const float4*)&Kb[(size_t)(k0 + krow[i]) * DD + kc4[i] * 4];
        }
        __syncthreads();
#pragma unroll
        for (int i = 0; i < 4; i++) *(float4*)&SB[krow[i]][kc4[i] * 4] = kv[i];
        if (t < 127) {
            int rel = q0 - k0 - 63 + t;
            rel = rel < -MAXREL ? -MAXREL : (rel > MAXREL ? MAXREL : rel);
            bias_s[t] = rtab[(rel + MAXREL) * HH + h];
        }
        __syncthreads();

        float s[4][4];
#pragma unroll
        for (int i = 0; i < 4; i++)
#pragma unroll
            for (int j = 0; j < 4; j++) s[i][j] = 0.f;

#pragma unroll
        for (int d4 = 0; d4 < 16; d4++) {
            float4 a[4], b[4];
#pragma unroll
            for (int i = 0; i < 4; i++) a[i] = *(const float4*)&SA[ty * 4 + i][d4 * 4];
#pragma unroll
            for (int j = 0; j < 4; j++) b[j] = *(const float4*)&SB[tx * 4 + j][d4 * 4];
#pragma unroll
            for (int i = 0; i < 4; i++)
#pragma unroll
                for (int j = 0; j < 4; j++)
                    s[i][j] += a[i].x * b[j].x + a[i].y * b[j].y +
                               a[i].z * b[j].z + a[i].w * b[j].w;
        }

#pragma unroll
        for (int i = 0; i < 4; i++) {
            int qi = q0 + ty * 4 + i;
#pragma unroll
            for (int j = 0; j < 4; j++) {
                int kj = k0 + tx * 4 + j;
                float v = s[i][j] * scale + bias_s[(ty * 4 + i) - (tx * 4 + j) + 63];
                s[i][j] = (kj > qi) ? -INFINITY : v;
            }
        }
        // raw score spill (read back in pass 2; hot in L2)
#pragma unroll
        for (int i = 0; i < 4; i++) {
            float4 sv = make_float4(s[i][0], s[i][1], s[i][2], s[i][3]);
            *(float4*)&attn_bh[(size_t)(q0 + ty * 4 + i) * SS + k0 + tx * 4] = sv;
        }
        // online softmax stats; each row owned by the 16 lanes of one ty group
#pragma unroll
        for (int i = 0; i < 4; i++) {
            float rm = fmaxf(fmaxf(s[i][0], s[i][1]), fmaxf(s[i][2], s[i][3]));
#pragma unroll
            for (int off = 8; off; off >>= 1)
                rm = fmaxf(rm, __shfl_xor_sync(0xffffffffu, rm, off));
            float mn = fmaxf(m[i], rm);
            float ps = __expf(s[i][0] - mn) + __expf(s[i][1] - mn) +
                       __expf(s[i][2] - mn) + __expf(s[i][3] - mn);
#pragma unroll
            for (int off = 8; off; off >>= 1)
                ps += __shfl_xor_sync(0xffffffffu, ps, off);
            l[i] = l[i] * __expf(m[i] - mn) + ps;
            m[i] = mn;
        }
    }

    float invl[4];
#pragma unroll
    for (int i = 0; i < 4; i++) invl[i] = 1.f / l[i];

    float o[4][4];
#pragma unroll
    for (int i = 0; i < 4; i++)
#pragma unroll
        for (int j = 0; j < 4; j++) o[i][j] = 0.f;

    // ---------------- PASS 2: p = exp(s-m)/l -> attn, O += P @ V -------------
    for (int kt = 0; kt < ntiles; kt++) {
        const int k0 = kt * 64;
        float4 vv[4]; int vrow[4], vc4[4];
#pragma unroll
        for (int i = 0; i < 4; i++) {
            int e = t + i * 256;
            vrow[i] = e >> 4; vc4[i] = e & 15;
            vv[i] = *(const float4*)&Vb[(size_t)(k0 + vrow[i]) * DD + vc4[i] * 4];
        }
        float4 p[4];
#pragma unroll
        for (int i = 0; i < 4; i++) {
            float4 sv = *(const float4*)&attn_bh[(size_t)(q0 + ty * 4 + i) * SS + k0 + tx * 4];
            p[i].x = __expf(sv.x - m[i]) * invl[i];
            p[i].y = __expf(sv.y - m[i]) * invl[i];
            p[i].z = __expf(sv.z - m[i]) * invl[i];
            p[i].w = __expf(sv.w - m[i]) * invl[i];
        }
        __syncthreads();
#pragma unroll
        for (int i = 0; i < 4; i++) *(float4*)&SB[vrow[i]][vc4[i] * 4] = vv[i];
#pragma unroll
        for (int i = 0; i < 4; i++) {
            *(float4*)&SA[ty * 4 + i][tx * 4] = p[i];                     // P tile
            *(float4*)&attn_bh[(size_t)(q0 + ty * 4 + i) * SS + k0 + tx * 4] = p[i];
        }
        __syncthreads();

#pragma unroll
        for (int k4 = 0; k4 < 16; k4++) {
            float4 a[4];
#pragma unroll
            for (int i = 0; i < 4; i++) a[i] = *(const float4*)&SA[ty * 4 + i][k4 * 4];
            float4 b0 = *(const float4*)&SB[k4 * 4 + 0][tx * 4];
            float4 b1 = *(const float4*)&SB[k4 * 4 + 1][tx * 4];
            float4 b2 = *(const float4*)&SB[k4 * 4 + 2][tx * 4];
            float4 b3 = *(const float4*)&SB[k4 * 4 + 3][tx * 4];
#pragma unroll
            for (int i = 0; i < 4; i++) {
                o[i][0] += a[i].x * b0.x + a[i].y * b1.x + a[i].z * b2.x + a[i].w * b3.x;
                o[i][1] += a[i].x * b0.y + a[i].y * b1.y + a[i].z * b2.y + a[i].w * b3.y;
                o[i][2] += a[i].x * b0.z + a[i].y * b1.z + a[i].z * b2.z + a[i].w * b3.z;
                o[i][3] += a[i].x * b0.w + a[i].y * b1.w + a[i].z * b2.w + a[i].w * b3.w;
            }
        }
    }

    // zero-fill strictly-causal-masked tiles (attn must be fully written)
    const float4 z4 = make_float4(0.f, 0.f, 0.f, 0.f);
    for (int kt = ntiles; kt < SS / 64; kt++) {
        const int k0 = kt * 64;
#pragma unroll
        for (int i = 0; i < 4; i++) {
            int e = t + i * 256;
            int row = e >> 4, c4 = e & 15;
            *(float4*)&attn_bh[(size_t)(q0 + row) * SS + k0 + c4 * 4] = z4;
        }
    }

    // write O heads
#pragma unroll
    for (int i = 0; i < 4; i++) {
        float4 ov = make_float4(o[i][0], o[i][1], o[i][2], o[i][3]);
        *(float4*)&g_Oh[((size_t)bh * SS + q0 + ty * 4 + i) * DD + tx * 4] = ov;
    }
}

// ---------------- attention, flash variant (no attn output needed) ----------
// Single pass, online O rescaling. No scratch, no attn writes.
// grid: (SS/64, BB*HH), block 256
__global__ __launch_bounds__(256) void attn_flash_kernel(const float* __restrict__ rtab)
{
    __shared__ float SA[64][68];
    __shared__ float SB[64][68];
    __shared__ float bias_s[128];

    const int q0 = blockIdx.x * 64;
    const int bh = blockIdx.y;
    const int h  = bh & (HH - 1);
    const int t  = threadIdx.x;
    const int ty = t >> 4, tx = t & 15;
    const float scale = 0.125f;

    const float* Qb = g_Qh + (size_t)bh * SS * DD;
    const float* Kb = g_Kh + (size_t)bh * SS * DD;
    const float* Vb = g_Vh + (size_t)bh * SS * DD;

    const int ntiles = (q0 >> 6) + 1;
    float m[4], l[4], o[4][4];
#pragma unroll
    for (int i = 0; i < 4; i++) {
        m[i] = -INFINITY; l[i] = 0.f;
#pragma unroll
        for (int j = 0; j < 4; j++) o[i][j] = 0.f;
    }

    for (int kt = 0; kt < ntiles; kt++) {
        const int k0 = kt * 64;
        __syncthreads();
        // SA = Q tile (reload each iter; L2-hot), SB = K tile
#pragma unroll
        for (int i = 0; i < 4; i++) {
            int e = t + i * 256;
            int row = e >> 4, c4 = e & 15;
            *(float4*)&SA[row][c4 * 4] = *(const float4*)&Qb[(size_t)(q0 + row) * DD + c4 * 4];
            *(float4*)&SB[row][c4 * 4] = *(const float4*)&Kb[(size_t)(k0 + row) * DD + c4 * 4];
        }
        if (t < 127) {
            int rel = q0 - k0 - 63 + t;
            rel = rel < -MAXREL ? -MAXREL : (rel > MAXREL ? MAXREL : rel);
            bias_s[t] = rtab[(rel + MAXREL) * HH + h];
        }
        __syncthreads();

        float s[4][4];
#pragma unroll
        for (int i = 0; i < 4; i++)
#pragma unroll
            for (int j = 0; j < 4; j++) s[i][j] = 0.f;
#pragma unroll
        for (int d4 = 0; d4 < 16; d4++) {
            float4 a[4], b[4];
#pragma unroll
            for (int i = 0; i < 4; i++) a[i] = *(const float4*)&SA[ty * 4 + i][d4 * 4];
#pragma unroll
            for (int j = 0; j < 4; j++) b[j] = *(const float4*)&SB[tx * 4 + j][d4 * 4];
#pragma unroll
            for (int i = 0; i < 4; i++)
#pragma unroll
                for (int j = 0; j < 4; j++)
                    s[i][j] += a[i].x * b[j].x + a[i].y * b[j].y +
                               a[i].z * b[j].z + a[i].w * b[j].w;
        }

#pragma unroll
        for (int i = 0; i < 4; i++) {
            int qi = q0 + ty * 4 + i;
#pragma unroll
            for (int j = 0; j < 4; j++) {
                int kj = k0 + tx * 4 + j;
                float v = s[i][j] * scale + bias_s[(ty * 4 + i) - (tx * 4 + j) + 63];
                s[i][j] = (kj > qi) ? -INFINITY : v;
            }
        }

        // online softmax update + O rescale; p left (unnormalized) in s[][]
#pragma unroll
        for (int i = 0; i < 4; i++) {
            float rm = fmaxf(fmaxf(s[i][0], s[i][1]), fmaxf(s[i][2], s[i][3]));
#pragma unroll
            for (int off = 8; off; off >>= 1)
                rm = fmaxf(rm, __shfl_xor_sync(0xffffffffu, rm, off));
            float mn = fmaxf(m[i], rm);
            float corr = __expf(m[i] - mn);
            s[i][0] = __expf(s[i][0] - mn);
            s[i][1] = __expf(s[i][1] - mn);
            s[i][2] = __expf(s[i][2] - mn);
            s[i][3] = __expf(s[i][3] - mn);
            float ps = s[i][0] + s[i][1] + s[i][2] + s[i][3];
#pragma unroll
            for (int off = 8; off; off >>= 1)
                ps += __shfl_xor_sync(0xffffffffu, ps, off);
            l[i] = l[i] * corr + ps;
            m[i] = mn;
#pragma unroll
            for (int j = 0; j < 4; j++) o[i][j] *= corr;
        }

        __syncthreads();
        // SA = P tile, SB = V tile
#pragma unroll
        for (int i = 0; i < 4; i++) {
            float4 pv = make_float4(s[i][0], s[i][1], s[i][2], s[i][3]);
            *(float4*)&SA[ty * 4 + i][tx * 4] = pv;
        }
#pragma unroll
        for (int i = 0; i < 4; i++) {
            int e = t + i * 256;
            int row = e >> 4, c4 = e & 15;
            *(float4*)&SB[row][c4 * 4] = *(const float4*)&Vb[(size_t)(k0 + row) * DD + c4 * 4];
        }
        __syncthreads();

#pragma unroll
        for (int k4 = 0; k4 < 16; k4++) {
            float4 a[4];
#pragma unroll
            for (int i = 0; i < 4; i++) a[i] = *(const float4*)&SA[ty * 4 + i][k4 * 4];
            float4 b0 = *(const float4*)&SB[k4 * 4 + 0][tx * 4];
            float4 b1 = *(const float4*)&SB[k4 * 4 + 1][tx * 4];
            float4 b2 = *(const float4*)&SB[k4 * 4 + 2][tx * 4];
            float4 b3 = *(const float4*)&SB[k4 * 4 + 3][tx * 4];
#pragma unroll
            for (int i = 0; i < 4; i++) {
                o[i][0] += a[i].x * b0.x + a[i].y * b1.x + a[i].z * b2.x + a[i].w * b3.x;
                o[i][1] += a[i].x * b0.y + a[i].y * b1.y + a[i].z * b2.y + a[i].w * b3.y;
                o[i][2] += a[i].x * b0.z + a[i].y * b1.z + a[i].z * b2.z + a[i].w * b3.z;
                o[i][3] += a[i].x * b0.w + a[i].y * b1.w + a[i].z * b2.w + a[i].w * b3.w;
            }
        }
    }

#pragma unroll
    for (int i = 0; i < 4; i++) {
        float inv = 1.f / l[i];
        float4 ov = make_float4(o[i][0] * inv, o[i][1] * inv, o[i][2] * inv, o[i][3] * inv);
        *(float4*)&g_Oh[((size_t)bh * SS + q0 + ty * 4 + i) * DD + tx * 4] = ov;
    }
}

// ---------------- output projection: Oh(reshaped) @ Wo^T + bo ---------------
// grid: (EE/64, (BB*SS)/64), block 256
__global__ __launch_bounds__(256) void out_proj_kernel(
    const float* __restrict__ Wo, const float* __restrict__ bo, float* __restrict__ out)
{
    __shared__ float As[16][68];
    __shared__ float Bs[16][68];

    const int m0 = blockIdx.y * 64;
    const int n0 = blockIdx.x * 64;
    const int t  = threadIdx.x;
    const int ty = t >> 4, tx = t & 15;
    const int lrow = t >> 2, lc4 = t & 3;

    float acc[4][4];
#pragma unroll
    for (int i = 0; i < 4; i++)
#pragma unroll
        for (int j = 0; j < 4; j++) acc[i][j] = 0.f;

    const int m = m0 + lrow;
    const int b_ = m >> 11, s_ = m & 2047;

    for (int k0 = 0; k0 < EE; k0 += 16) {
        int kcol = k0 + lc4 * 4;
        int h = kcol >> 6, d = kcol & 63;
        float4 av = *(const float4*)&g_Oh[(((size_t)b_ * HH + h) * SS + s_) * DD + d];
        float4 wv = *(const float4*)&Wo[(size_t)(n0 + lrow) * EE + kcol];
        __syncthreads();
        As[lc4 * 4 + 0][lrow] = av.x; As[lc4 * 4 + 1][lrow] = av.y;
        As[lc4 * 4 + 2][lrow] = av.z; As[lc4 * 4 + 3][lrow] = av.w;
        Bs[lc4 * 4 + 0][lrow] = wv.x; Bs[lc4 * 4 + 1][lrow] = wv.y;
        Bs[lc4 * 4 + 2][lrow] = wv.z; Bs[lc4 * 4 + 3][lrow] = wv.w;
        __syncthreads();
#pragma unroll
        for (int kk = 0; kk < 16; kk++) {
            float4 a = *(const float4*)&As[kk][ty * 4];
            float4 b = *(const float4*)&Bs[kk][tx * 4];
            float ar[4] = {a.x, a.y, a.z, a.w};
            float br[4] = {b.x, b.y, b.z, b.w};
#pragma unroll
            for (int i = 0; i < 4; i++)
#pragma unroll
                for (int j = 0; j < 4; j++) acc[i][j] += ar[i] * br[j];
        }
    }

#pragma unroll
    for (int i = 0; i < 4; i++) {
        int mm = m0 + ty * 4 + i;
#pragma unroll
        for (int j = 0; j < 4; j++) {
            int n = n0 + tx * 4 + j;
            out[(size_t)mm * EE + n] = acc[i][j] + bo[n];
        }
    }
}

// ---------------- launch ----------------------------------------------------
extern "C" void kernel_launch(void* const* d_in, const int* in_sizes, int n_in,
                              void* d_out, int out_size)
{
    (void)in_sizes; (void)n_in;
    const float* query = (const float*)d_in[0];
    const float* key   = (const float*)d_in[1];
    const float* value = (const float*)d_in[2];
    const float* Wq    = (const float*)d_in[3];
    const float* bq    = (const float*)d_in[4];
    const float* Wk    = (const float*)d_in[5];
    const float* bk    = (const float*)d_in[6];
    const float* Wv    = (const float*)d_in[7];
    const float* bv    = (const float*)d_in[8];
    const float* Wo    = (const float*)d_in[9];
    const float* bo    = (const float*)d_in[10];
    const float* rtab  = (const float*)d_in[11];

    float* out = (float*)d_out;
    const size_t OUTN  = (size_t)BB * SS * EE;
    const size_t ATTNN = (size_t)BB * HH * SS * SS;

    proj_qkv_kernel<<<dim3(EE / 64, (BB * SS) / 64, 3), 256>>>(
        query, key, value, Wq, bq, Wk, bk, Wv, bv);

    if ((size_t)out_size >= OUTN + ATTNN) {
        // harness expects (out, attn) concatenated: spill/normalize into d_out
        float* attn = out + OUTN;
        attn_spill_kernel<<<dim3(SS / 64, BB * HH), 256>>>(rtab, attn);
    } else {
        // out-only: single-pass flash attention, no attn materialization
        attn_flash_kernel<<<dim3(SS / 64, BB * HH), 256>>>(rtab);
    }

    out_proj_kernel<<<dim3(EE / 64, (BB * SS) / 64), 256>>>(Wo, bo, out);
}